// round 4
// baseline (speedup 1.0000x reference)
#include <cuda_runtime.h>
#include <math.h>
#include <stdint.h>

// Problem constants (validated against in_sizes at launch)
#define NN 100000
#define NE 1600000
#define KDIM 1433
#define HID 50
#define NPAD 52
#define ODIM 7

// ---------------- scratch (static __device__, no allocation) ----------------
__device__ float g_h1[(size_t)NN * HID];     // x @ W1
__device__ float g_h2[(size_t)NN * ODIM];    // relu(agg1+b1) @ W2
__device__ float g_dinv[NN];
__device__ int   g_cnt[NN];
__device__ int   g_cursor[NN];
__device__ int   g_rowptr[NN + 1];
__device__ int   g_part[128];
__device__ int   g_csr[NE];

// ---------------- degree / CSR build ----------------
__global__ void k_init(int n) {
    int i = blockIdx.x * blockDim.x + threadIdx.x;
    if (i < n) { g_cnt[i] = 0; g_cursor[i] = 0; }
}

__global__ void k_hist(const int* __restrict__ col, int e) {
    int i = blockIdx.x * blockDim.x + threadIdx.x;
    if (i < e) atomicAdd(&g_cnt[col[i]], 1);
}

__global__ void k_dinv(int n) {
    int i = blockIdx.x * blockDim.x + threadIdx.x;
    if (i < n) {
        float deg = (float)(g_cnt[i] + 1);  // +1 self loop
        g_dinv[i] = rsqrtf(deg);
    }
}

// block-local exclusive scan (1024/block) + block totals
__global__ void k_scan1(int n) {
    int t = threadIdx.x, b = blockIdx.x;
    int i = b * 1024 + t;
    int lane = t & 31, warp = t >> 5;
    int val = (i < n) ? g_cnt[i] : 0;
    int v = val;
    #pragma unroll
    for (int d = 1; d < 32; d <<= 1) {
        int u = __shfl_up_sync(0xffffffffu, v, d);
        if (lane >= d) v += u;
    }
    __shared__ int wsum[32];
    if (lane == 31) wsum[warp] = v;
    __syncthreads();
    if (warp == 0) {
        int s = wsum[lane];
        #pragma unroll
        for (int d = 1; d < 32; d <<= 1) {
            int u = __shfl_up_sync(0xffffffffu, s, d);
            if (lane >= d) s += u;
        }
        wsum[lane] = s;
    }
    __syncthreads();
    int woff = (warp == 0) ? 0 : wsum[warp - 1];
    int incl = v + woff;
    if (i < n) g_rowptr[i] = incl - val;   // exclusive within block
    if (t == 1023) g_part[b] = incl;       // block total
}

// single-warp scan of block partials (nb <= 128 -> 4 chunks of 32)
__global__ void k_scan2(int nb) {
    int lane = threadIdx.x;
    int base = 0;
    for (int c = 0; c < nb; c += 32) {
        int idx = c + lane;
        int val = (idx < nb) ? g_part[idx] : 0;
        int v = val;
        #pragma unroll
        for (int d = 1; d < 32; d <<= 1) {
            int u = __shfl_up_sync(0xffffffffu, v, d);
            if (lane >= d) v += u;
        }
        if (idx < nb) g_part[idx] = base + v - val;  // exclusive
        int tot = __shfl_sync(0xffffffffu, v, 31);
        base += tot;
    }
}

__global__ void k_scan3(int n, int e) {
    int i = blockIdx.x * blockDim.x + threadIdx.x;
    if (i < n) g_rowptr[i] += g_part[i >> 10];
    if (i == 0) g_rowptr[n] = e;
}

__global__ void k_fill(const int* __restrict__ row, const int* __restrict__ col, int e) {
    int i = blockIdx.x * blockDim.x + threadIdx.x;
    if (i < e) {
        int d = col[i];
        int pos = atomicAdd(&g_cursor[d], 1);
        g_csr[g_rowptr[d] + pos] = row[i];
    }
}

// ---------------- GEMM1: h1[M,50] = x[M,1433] @ W1[1433,50] ----------------
__global__ void __launch_bounds__(128) k_gemm1(const float* __restrict__ x,
                                               const float* __restrict__ W1,
                                               int M) {
    __shared__ float xs[128][33];
    __shared__ float ws[32][NPAD];
    int t = threadIdx.x;
    int row0 = blockIdx.x * 128;
    int row = row0 + t;

    float acc[NPAD];
    #pragma unroll
    for (int c = 0; c < NPAD; c++) acc[c] = 0.f;

    for (int k0 = 0; k0 < KDIM; k0 += 32) {
        // load x tile: 128 rows x 32 k, coalesced over k
        #pragma unroll
        for (int i = 0; i < 32; i++) {
            int r = i * 4 + (t >> 5);
            int kk = t & 31;
            int gr = row0 + r, gk = k0 + kk;
            float v = 0.f;
            if (gr < M && gk < KDIM) v = x[(size_t)gr * KDIM + gk];
            xs[r][kk] = v;
        }
        // load W1 tile: 32 x 52 (zero-padded)
        #pragma unroll
        for (int i = 0; i < 13; i++) {
            int idx = i * 128 + t;
            int kk = idx / NPAD;
            int c  = idx - kk * NPAD;
            int gk = k0 + kk;
            float v = 0.f;
            if (c < HID && gk < KDIM) v = W1[(size_t)gk * HID + c];
            ws[kk][c] = v;
        }
        __syncthreads();
        #pragma unroll 4
        for (int kk = 0; kk < 32; kk++) {
            float xv = xs[t][kk];
            #pragma unroll
            for (int c4 = 0; c4 < 13; c4++) {
                float4 w = *reinterpret_cast<const float4*>(&ws[kk][c4 * 4]);
                acc[c4 * 4 + 0] = fmaf(xv, w.x, acc[c4 * 4 + 0]);
                acc[c4 * 4 + 1] = fmaf(xv, w.y, acc[c4 * 4 + 1]);
                acc[c4 * 4 + 2] = fmaf(xv, w.z, acc[c4 * 4 + 2]);
                acc[c4 * 4 + 3] = fmaf(xv, w.w, acc[c4 * 4 + 3]);
            }
        }
        __syncthreads();
    }

    if (row < M) {
        float* hp = g_h1 + (size_t)row * HID;
        #pragma unroll
        for (int c = 0; c < HID; c += 2) {
            *reinterpret_cast<float2*>(hp + c) = make_float2(acc[c], acc[c + 1]);
        }
    }
}

// ---------------- agg1 + bias + relu + GEMM2 fused ----------------
// warp per node: segmented normalized sum of h1 rows, then h2 = relu(.+b1) @ W2
__global__ void k_agg1(const float* __restrict__ b1,
                       const float* __restrict__ W2,
                       int n) {
    int w = (blockIdx.x * blockDim.x + threadIdx.x) >> 5;
    int lane = threadIdx.x & 31;
    if (w >= n) return;

    int s0 = g_rowptr[w], s1 = g_rowptr[w + 1];
    float di = g_dinv[w];
    int f1 = lane + 32;
    bool has1 = (f1 < HID);

    float a0 = 0.f, a1 = 0.f;
    for (int e = s0; e < s1; e++) {
        int s = g_csr[e];
        float nrm = g_dinv[s] * di;
        const float* hp = g_h1 + (size_t)s * HID;
        a0 = fmaf(__ldg(hp + lane), nrm, a0);
        if (has1) a1 = fmaf(__ldg(hp + f1), nrm, a1);
    }
    {   // self loop
        float nrm = di * di;
        const float* hp = g_h1 + (size_t)w * HID;
        a0 = fmaf(hp[lane], nrm, a0);
        if (has1) a1 = fmaf(hp[f1], nrm, a1);
    }
    float r0 = fmaxf(a0 + b1[lane], 0.f);
    float r1 = has1 ? fmaxf(a1 + b1[f1], 0.f) : 0.f;

    // h2[w][c] = sum_j relu[j] * W2[j][c]
    float p[ODIM];
    #pragma unroll
    for (int c = 0; c < ODIM; c++) {
        float v = r0 * W2[lane * ODIM + c];
        if (has1) v = fmaf(r1, W2[f1 * ODIM + c], v);
        p[c] = v;
    }
    #pragma unroll
    for (int c = 0; c < ODIM; c++) {
        #pragma unroll
        for (int d = 16; d > 0; d >>= 1)
            p[c] += __shfl_xor_sync(0xffffffffu, p[c], d);
    }
    if (lane == 0) {
        float* op = g_h2 + (size_t)w * ODIM;
        #pragma unroll
        for (int c = 0; c < ODIM; c++) op[c] = p[c];
    }
}

// ---------------- agg2 + bias + sigmoid ----------------
__global__ void k_agg2(const float* __restrict__ b2,
                       float* __restrict__ out,
                       int n) {
    int w = (blockIdx.x * blockDim.x + threadIdx.x) >> 5;
    int lane = threadIdx.x & 31;
    if (w >= n) return;

    int s0 = g_rowptr[w], s1 = g_rowptr[w + 1];
    float di = g_dinv[w];
    bool act = (lane < ODIM);
    float acc = 0.f;
    for (int e = s0; e < s1; e++) {
        int s = g_csr[e];
        float nrm = g_dinv[s] * di;
        if (act) acc = fmaf(__ldg(&g_h2[(size_t)s * ODIM + lane]), nrm, acc);
    }
    if (act) {
        acc = fmaf(g_h2[(size_t)w * ODIM + lane], di * di, acc);
        float z = acc + b2[lane];
        out[(size_t)w * ODIM + lane] = 1.f / (1.f + expf(-z));
    }
}

// ---------------- launch ----------------
extern "C" void kernel_launch(void* const* d_in, const int* in_sizes, int n_in,
                              void* d_out, int out_size) {
    // defaults per metadata order: x, edge_index, W1, b1, W2, b2
    const float* x  = (const float*)d_in[0];
    const int*   ei = (const int*)d_in[1];
    const float* W1 = (const float*)d_in[2];
    const float* b1 = (const float*)d_in[3];
    const float* W2 = (const float*)d_in[4];
    const float* b2 = (const float*)d_in[5];
    // defensive: identify by element count (all sizes distinct)
    for (int i = 0; i < n_in; i++) {
        long s = in_sizes[i];
        if (s == (long)NN * KDIM)      x  = (const float*)d_in[i];
        else if (s == 2L * NE)         ei = (const int*)d_in[i];
        else if (s == (long)KDIM*HID)  W1 = (const float*)d_in[i];
        else if (s == HID)             b1 = (const float*)d_in[i];
        else if (s == HID * ODIM)      W2 = (const float*)d_in[i];
        else if (s == ODIM)            b2 = (const float*)d_in[i];
    }
    const int* row = ei;        // edge_index[0]
    const int* col = ei + NE;   // edge_index[1]
    float* out = (float*)d_out;
    (void)out_size;

    const int n = NN, e = NE;

    k_init<<<(n + 255) / 256, 256>>>(n);
    k_hist<<<(e + 255) / 256, 256>>>(col, e);
    k_dinv<<<(n + 255) / 256, 256>>>(n);

    int nb = (n + 1023) / 1024;
    k_scan1<<<nb, 1024>>>(n);
    k_scan2<<<1, 32>>>(nb);
    k_scan3<<<(n + 255) / 256, 256>>>(n, e);
    k_fill<<<(e + 255) / 256, 256>>>(row, col, e);

    k_gemm1<<<(n + 127) / 128, 128>>>(x, W1, n);

    int aggBlocks = (n * 32 + 255) / 256;
    k_agg1<<<aggBlocks, 256>>>(b1, W2, n);
    k_agg2<<<aggBlocks, 256>>>(b2, out, n);
}

// round 13
// speedup vs baseline: 1.3825x; 1.3825x over previous
#include <cuda_runtime.h>
#include <cuda_bf16.h>
#include <math.h>
#include <stdint.h>

#define NN 100000
#define NE 1600000
#define KDIM 1433
#define HID 50
#define ODIM 7

#define NCHUNK 23
#define KPAD (NCHUNK * 64)   // 1472

// ---------------- scratch (static __device__, no allocation) ----------------
__device__ float g_h1[(size_t)NN * HID];
__device__ float g_h2[(size_t)NN * ODIM];
__device__ float g_dinv[NN];
__device__ int   g_cnt[NN];
__device__ int   g_cursor[NN];
__device__ int   g_rowptr[NN + 1];
__device__ int   g_part[128];
__device__ int   g_csr[NE];
__device__ __align__(16) __nv_bfloat16 g_w1hi[64 * KPAD];
__device__ __align__(16) __nv_bfloat16 g_w1lo[64 * KPAD];

// ---------------- helpers ----------------
__device__ __forceinline__ uint32_t smem_u32(const void* p) {
    uint32_t a;
    asm("{ .reg .u64 t; cvta.to.shared.u64 t, %1; cvt.u32.u64 %0, t; }" : "=r"(a) : "l"(p));
    return a;
}
#define SWZ(o) ((o) ^ (((o) >> 3) & 0x70))

#define LDSM_X4(r0, r1, r2, r3, addr) \
    asm volatile("ldmatrix.sync.aligned.m8n8.x4.shared.b16 {%0,%1,%2,%3}, [%4];" \
        : "=r"(r0), "=r"(r1), "=r"(r2), "=r"(r3) : "r"(addr))

__device__ __forceinline__ void mma16816(float* c,
    uint32_t a0, uint32_t a1, uint32_t a2, uint32_t a3,
    uint32_t b0, uint32_t b1) {
    asm volatile("mma.sync.aligned.m16n8k16.row.col.f32.bf16.bf16.f32 "
        "{%0,%1,%2,%3}, {%4,%5,%6,%7}, {%8,%9}, {%0,%1,%2,%3};"
        : "+f"(c[0]), "+f"(c[1]), "+f"(c[2]), "+f"(c[3])
        : "r"(a0), "r"(a1), "r"(a2), "r"(a3), "r"(b0), "r"(b1));
}

// ---------------- degree / CSR build ----------------
__global__ void k_init(int n) {
    int i = blockIdx.x * blockDim.x + threadIdx.x;
    if (i < n) { g_cnt[i] = 0; g_cursor[i] = 0; }
}
__global__ void k_hist(const int* __restrict__ col, int e) {
    int i = blockIdx.x * blockDim.x + threadIdx.x;
    if (i < e) atomicAdd(&g_cnt[col[i]], 1);
}
__global__ void k_dinv(int n) {
    int i = blockIdx.x * blockDim.x + threadIdx.x;
    if (i < n) g_dinv[i] = rsqrtf((float)(g_cnt[i] + 1));
}
__global__ void k_scan1(int n) {
    int t = threadIdx.x, b = blockIdx.x;
    int i = b * 1024 + t;
    int lane = t & 31, warp = t >> 5;
    int val = (i < n) ? g_cnt[i] : 0;
    int v = val;
    #pragma unroll
    for (int d = 1; d < 32; d <<= 1) {
        int u = __shfl_up_sync(0xffffffffu, v, d);
        if (lane >= d) v += u;
    }
    __shared__ int wsum[32];
    if (lane == 31) wsum[warp] = v;
    __syncthreads();
    if (warp == 0) {
        int s = wsum[lane];
        #pragma unroll
        for (int d = 1; d < 32; d <<= 1) {
            int u = __shfl_up_sync(0xffffffffu, s, d);
            if (lane >= d) s += u;
        }
        wsum[lane] = s;
    }
    __syncthreads();
    int woff = (warp == 0) ? 0 : wsum[warp - 1];
    int incl = v + woff;
    if (i < n) g_rowptr[i] = incl - val;
    if (t == 1023) g_part[b] = incl;
}
__global__ void k_scan2(int nb) {
    int lane = threadIdx.x;
    int base = 0;
    for (int c = 0; c < nb; c += 32) {
        int idx = c + lane;
        int val = (idx < nb) ? g_part[idx] : 0;
        int v = val;
        #pragma unroll
        for (int d = 1; d < 32; d <<= 1) {
            int u = __shfl_up_sync(0xffffffffu, v, d);
            if (lane >= d) v += u;
        }
        if (idx < nb) g_part[idx] = base + v - val;
        int tot = __shfl_sync(0xffffffffu, v, 31);
        base += tot;
    }
}
__global__ void k_scan3(int n, int e) {
    int i = blockIdx.x * blockDim.x + threadIdx.x;
    if (i < n) g_rowptr[i] += g_part[i >> 10];
    if (i == 0) g_rowptr[n] = e;
}
__global__ void k_fill(const int* __restrict__ row, const int* __restrict__ col, int e) {
    int i = blockIdx.x * blockDim.x + threadIdx.x;
    if (i < e) {
        int d = col[i];
        int pos = atomicAdd(&g_cursor[d], 1);
        g_csr[g_rowptr[d] + pos] = row[i];
    }
}

// ---------------- W1 split prologue: [64 rows N][KPAD] K-major bf16 hi/lo ----------------
__global__ void k_prepw(const float* __restrict__ W1) {
    int i = blockIdx.x * blockDim.x + threadIdx.x;
    if (i >= 64 * KPAD) return;
    int c = i / KPAD, k = i - c * KPAD;
    float v = (c < HID && k < KDIM) ? W1[k * HID + c] : 0.f;
    __nv_bfloat16 hi = __float2bfloat16(v);
    g_w1hi[i] = hi;
    g_w1lo[i] = __float2bfloat16(v - __bfloat162float(hi));
}

// ---------------- GEMM1 via mma.sync bf16x3: h1[M,50] = x[M,1433] @ W1 ----------------
// CTA: 128 threads (4 warps), M-tile 64 (16 rows/warp), N-tile 56 (7 n8 tiles), K chunk 64.
__global__ void __launch_bounds__(128) k_gemm1_mma(const float* __restrict__ x, int M) {
    __shared__ __align__(128) __nv_bfloat16 s_ahi[64 * 64];
    __shared__ __align__(128) __nv_bfloat16 s_alo[64 * 64];
    __shared__ __align__(128) __nv_bfloat16 s_bhi[64 * 64];
    __shared__ __align__(128) __nv_bfloat16 s_blo[64 * 64];
    uint32_t ahi = smem_u32(s_ahi), alo = smem_u32(s_alo);
    uint32_t bhi = smem_u32(s_bhi), blo = smem_u32(s_blo);

    int tid = threadIdx.x;
    int wid = tid >> 5, lane = tid & 31;
    int row0 = blockIdx.x * 64;

    float acc[7][4];
    #pragma unroll
    for (int nt = 0; nt < 7; nt++)
        #pragma unroll
        for (int j = 0; j < 4; j++) acc[nt][j] = 0.f;

    const int f4    = tid & 15;   // 4-float group index within 64-wide K chunk
    const int rbase = tid >> 4;   // 0..7

    // ldmatrix lane roles
    const int quad = lane >> 3, qr = lane & 7;
    const int a_row   = wid * 16 + (quad & 1) * 8 + qr;
    const int a_kb8   = (quad >> 1) * 8;
    const int b_r     = (quad >> 1) * 8 + qr;
    const int b_kb8   = (quad & 1) * 8;

    for (int c = 0; c < NCHUNK; c++) {
        int k0 = c * 64;
        __syncthreads();   // protect previous iteration's SMEM reads

        // --- load A chunk [64 rows x 64 K] fp32 -> bf16 hi/lo, swizzled SMEM ---
        // NOTE: x rows are only 4-byte aligned (KDIM=1433 odd) -> scalar loads only.
        #pragma unroll
        for (int it = 0; it < 8; it++) {
            int row = it * 8 + rbase;
            int grow = row0 + row;
            int gk = k0 + f4 * 4;
            float v0 = 0.f, v1 = 0.f, v2 = 0.f, v3 = 0.f;
            if (grow < M) {
                const float* p = x + (size_t)grow * KDIM + gk;
                if (gk + 3 < KDIM) {
                    v0 = p[0]; v1 = p[1]; v2 = p[2]; v3 = p[3];
                } else if (gk < KDIM) {
                    v0 = p[0];
                    if (gk + 1 < KDIM) v1 = p[1];
                    if (gk + 2 < KDIM) v2 = p[2];
                }
            }
            __nv_bfloat16 h0 = __float2bfloat16(v0), h1b = __float2bfloat16(v1);
            __nv_bfloat16 h2 = __float2bfloat16(v2), h3  = __float2bfloat16(v3);
            __nv_bfloat16 l0 = __float2bfloat16(v0 - __bfloat162float(h0));
            __nv_bfloat16 l1 = __float2bfloat16(v1 - __bfloat162float(h1b));
            __nv_bfloat16 l2 = __float2bfloat16(v2 - __bfloat162float(h2));
            __nv_bfloat16 l3 = __float2bfloat16(v3 - __bfloat162float(h3));
            uint32_t hA = (uint32_t)__bfloat16_as_ushort(h0) | ((uint32_t)__bfloat16_as_ushort(h1b) << 16);
            uint32_t hB = (uint32_t)__bfloat16_as_ushort(h2) | ((uint32_t)__bfloat16_as_ushort(h3) << 16);
            uint32_t lA = (uint32_t)__bfloat16_as_ushort(l0) | ((uint32_t)__bfloat16_as_ushort(l1) << 16);
            uint32_t lB = (uint32_t)__bfloat16_as_ushort(l2) | ((uint32_t)__bfloat16_as_ushort(l3) << 16);
            uint32_t off = SWZ(row * 128 + f4 * 8);
            asm volatile("st.shared.v2.b32 [%0], {%1,%2};" :: "r"(ahi + off), "r"(hA), "r"(hB));
            asm volatile("st.shared.v2.b32 [%0], {%1,%2};" :: "r"(alo + off), "r"(lA), "r"(lB));
        }

        // --- load B chunk [64 n x 64 K] bf16 hi/lo from presplit arrays ---
        #pragma unroll
        for (int j = 0; j < 8; j++) {
            int idx = tid + j * 128;          // 0..1023
            int arr = idx >> 9;               // 0: hi, 1: lo
            int e2  = idx & 511;
            int rb  = e2 >> 3, u4 = e2 & 7;
            const __nv_bfloat16* src = (arr ? g_w1lo : g_w1hi) + rb * KPAD + k0 + u4 * 8;
            uint4 v = *reinterpret_cast<const uint4*>(src);
            uint32_t dst = (arr ? blo : bhi) + SWZ(rb * 128 + u4 * 16);
            asm volatile("st.shared.v4.b32 [%0], {%1,%2,%3,%4};"
                         :: "r"(dst), "r"(v.x), "r"(v.y), "r"(v.z), "r"(v.w));
        }

        __syncthreads();

        // --- compute: 4 k16 steps ---
        #pragma unroll
        for (int ks = 0; ks < 4; ks++) {
            int kbyte = (ks * 16 + a_kb8) * 2;
            uint32_t a_off = SWZ(a_row * 128 + kbyte);
            uint32_t ah0, ah1, ah2, ah3, al0, al1, al2, al3;
            LDSM_X4(ah0, ah1, ah2, ah3, ahi + a_off);
            LDSM_X4(al0, al1, al2, al3, alo + a_off);

            int bkbyte = (ks * 16 + b_kb8) * 2;
            #pragma unroll
            for (int ntp = 0; ntp < 4; ntp++) {
                uint32_t b_off = SWZ((ntp * 16 + b_r) * 128 + bkbyte);
                uint32_t bh0, bh1, bh2, bh3, bl0, bl1, bl2, bl3;
                LDSM_X4(bh0, bh1, bh2, bh3, bhi + b_off);
                LDSM_X4(bl0, bl1, bl2, bl3, blo + b_off);
                int nt0 = ntp * 2;
                mma16816(acc[nt0], ah0, ah1, ah2, ah3, bh0, bh1);
                mma16816(acc[nt0], ah0, ah1, ah2, ah3, bl0, bl1);
                mma16816(acc[nt0], al0, al1, al2, al3, bh0, bh1);
                if (nt0 + 1 < 7) {
                    mma16816(acc[nt0 + 1], ah0, ah1, ah2, ah3, bh2, bh3);
                    mma16816(acc[nt0 + 1], ah0, ah1, ah2, ah3, bl2, bl3);
                    mma16816(acc[nt0 + 1], al0, al1, al2, al3, bh2, bh3);
                }
            }
        }
    }

    // --- epilogue: write h1 ---
    int gcol0 = (lane & 3) * 2;
    int grow = row0 + wid * 16 + (lane >> 2);
    #pragma unroll
    for (int nt = 0; nt < 7; nt++) {
        int col = nt * 8 + gcol0;
        if (col < HID) {
            if (grow < M) {
                float* p = g_h1 + (size_t)grow * HID + col;
                p[0] = acc[nt][0];
                p[1] = acc[nt][1];
            }
            if (grow + 8 < M) {
                float* p = g_h1 + (size_t)(grow + 8) * HID + col;
                p[0] = acc[nt][2];
                p[1] = acc[nt][3];
            }
        }
    }
}

// ---------------- agg1 + bias + relu + GEMM2 fused ----------------
__global__ void k_agg1(const float* __restrict__ b1,
                       const float* __restrict__ W2,
                       int n) {
    int w = (blockIdx.x * blockDim.x + threadIdx.x) >> 5;
    int lane = threadIdx.x & 31;
    if (w >= n) return;

    int s0 = g_rowptr[w], s1 = g_rowptr[w + 1];
    float di = g_dinv[w];
    int f1 = lane + 32;
    bool has1 = (f1 < HID);

    float a0 = 0.f, a1 = 0.f;
    for (int e = s0; e < s1; e++) {
        int s = g_csr[e];
        float nrm = g_dinv[s] * di;
        const float* hp = g_h1 + (size_t)s * HID;
        a0 = fmaf(__ldg(hp + lane), nrm, a0);
        if (has1) a1 = fmaf(__ldg(hp + f1), nrm, a1);
    }
    {
        float nrm = di * di;
        const float* hp = g_h1 + (size_t)w * HID;
        a0 = fmaf(hp[lane], nrm, a0);
        if (has1) a1 = fmaf(hp[f1], nrm, a1);
    }
    float r0 = fmaxf(a0 + b1[lane], 0.f);
    float r1 = has1 ? fmaxf(a1 + b1[f1], 0.f) : 0.f;

    float p[ODIM];
    #pragma unroll
    for (int c = 0; c < ODIM; c++) {
        float v = r0 * W2[lane * ODIM + c];
        if (has1) v = fmaf(r1, W2[f1 * ODIM + c], v);
        p[c] = v;
    }
    #pragma unroll
    for (int c = 0; c < ODIM; c++) {
        #pragma unroll
        for (int d = 16; d > 0; d >>= 1)
            p[c] += __shfl_xor_sync(0xffffffffu, p[c], d);
    }
    if (lane == 0) {
        float* op = g_h2 + (size_t)w * ODIM;
        #pragma unroll
        for (int c = 0; c < ODIM; c++) op[c] = p[c];
    }
}

// ---------------- agg2 + bias + sigmoid ----------------
__global__ void k_agg2(const float* __restrict__ b2,
                       float* __restrict__ out,
                       int n) {
    int w = (blockIdx.x * blockDim.x + threadIdx.x) >> 5;
    int lane = threadIdx.x & 31;
    if (w >= n) return;

    int s0 = g_rowptr[w], s1 = g_rowptr[w + 1];
    float di = g_dinv[w];
    bool act = (lane < ODIM);
    float acc = 0.f;
    for (int e = s0; e < s1; e++) {
        int s = g_csr[e];
        float nrm = g_dinv[s] * di;
        if (act) acc = fmaf(__ldg(&g_h2[(size_t)s * ODIM + lane]), nrm, acc);
    }
    if (act) {
        acc = fmaf(g_h2[(size_t)w * ODIM + lane], di * di, acc);
        float z = acc + b2[lane];
        out[(size_t)w * ODIM + lane] = 1.f / (1.f + expf(-z));
    }
}

// ---------------- launch ----------------
extern "C" void kernel_launch(void* const* d_in, const int* in_sizes, int n_in,
                              void* d_out, int out_size) {
    const float* x  = (const float*)d_in[0];
    const int*   ei = (const int*)d_in[1];
    const float* W1 = (const float*)d_in[2];
    const float* b1 = (const float*)d_in[3];
    const float* W2 = (const float*)d_in[4];
    const float* b2 = (const float*)d_in[5];
    for (int i = 0; i < n_in; i++) {
        long s = in_sizes[i];
        if (s == (long)NN * KDIM)      x  = (const float*)d_in[i];
        else if (s == 2L * NE)         ei = (const int*)d_in[i];
        else if (s == (long)KDIM*HID)  W1 = (const float*)d_in[i];
        else if (s == HID)             b1 = (const float*)d_in[i];
        else if (s == HID * ODIM)      W2 = (const float*)d_in[i];
        else if (s == ODIM)            b2 = (const float*)d_in[i];
    }
    const int* row = ei;
    const int* col = ei + NE;
    float* out = (float*)d_out;
    (void)out_size;

    const int n = NN, e = NE;

    k_init<<<(n + 255) / 256, 256>>>(n);
    k_hist<<<(e + 255) / 256, 256>>>(col, e);
    k_dinv<<<(n + 255) / 256, 256>>>(n);

    int nb = (n + 1023) / 1024;
    k_scan1<<<nb, 1024>>>(n);
    k_scan2<<<1, 32>>>(nb);
    k_scan3<<<(n + 255) / 256, 256>>>(n, e);
    k_fill<<<(e + 255) / 256, 256>>>(row, col, e);

    k_prepw<<<(64 * KPAD + 255) / 256, 256>>>(W1);
    k_gemm1_mma<<<(n + 63) / 64, 128>>>(x, n);

    int aggBlocks = (n * 32 + 255) / 256;
    k_agg1<<<aggBlocks, 256>>>(b1, W2, n);
    k_agg2<<<aggBlocks, 256>>>(b2, out, n);
}